// round 16
// baseline (speedup 1.0000x reference)
#include <cuda_runtime.h>
#include <cuda_fp16.h>
#include <math.h>
#include <stdint.h>

#define HH    512
#define NPIX  (HH*HH)
#define FD    128
#define NR    363
#define BM    32
#define GEMM_THREADS 256
#define GEMM_GRID 592      // 4 per SM: 2 types x 2 N-halves x 148
#define TYPE_GRID 148

// k_gemm smem layout (4 CTAs/SM, ~49KB each)
#define OFF_P    0                           // int[32]
#define OFF_RING 128                         // int[32]
#define OFF_A    1024                        // 2 segs: Xr, Xi
#define SEGA     8192                        // 32 rows x 256B fp16
#define OFF_B    (OFF_A + 2*SEGA)            // 17408
#define MATB     16384                       // 64n x 256B fp16 (N-half)
#define SMEM_TOTAL (OFF_B + 2*MATB)          // 50176 (~49KB)

// ---------------- device scratch ----------------
__device__ float g_sum_re[NR*FD];
__device__ float g_sum_im[NR*FD];
__device__ float g_mean_re[NR*FD];
__device__ float g_mean_im[NR*FD];
__device__ int   g_rcount[NR];
__device__ int   g_ucnt[NR];
__device__ int   g_base[NR+1];     // uncor ring bases (for ringsum)
__device__ int   g_cur[2*NR];      // scatter cursors
__device__ int   g_cnt[2];
__device__ int   g_list[2][NPIX];  // both lists ring-grouped
__device__ __align__(16) __half g_Wf[4][FD*FD];   // 0=w1re 1=w1im 2=w2re 3=w2im, [n*128+k]

// ---------------- helpers ----------------
__device__ __forceinline__ int ring_of(int p) {
    int i = (p >> 9) - 256;
    int j = (p & 511) - 256;
    int q = i*i + j*j;
    int s = __float2int_rd(sqrtf((float)q));
    while (s*s > q) --s;
    while ((s+1)*(s+1) <= q) ++s;
    return s;
}

__device__ __forceinline__ uint32_t smem_u32(const void* p) {
    uint32_t a;
    asm("{ .reg .u64 t; cvta.to.shared.u64 t, %1; cvt.u32.u64 %0, t; }" : "=r"(a) : "l"(p));
    return a;
}

// 16B-unit XOR swizzle within 256B rows
__device__ __forceinline__ int phys_unit(int u, int row) {
    return (u & 8) | ((u & 7) ^ (row & 7));
}

#define LDSM_X4(r, addr) \
    asm volatile("ldmatrix.sync.aligned.m8n8.x4.shared.b16 {%0,%1,%2,%3}, [%4];" \
        : "=r"((r)[0]), "=r"((r)[1]), "=r"((r)[2]), "=r"((r)[3]) : "r"(addr))

__device__ __forceinline__ void mma4(float* d, const uint32_t* a, uint32_t b0, uint32_t b1) {
    asm volatile("mma.sync.aligned.m16n8k16.row.col.f32.f16.f16.f32 "
        "{%0,%1,%2,%3}, {%4,%5,%6,%7}, {%8,%9}, {%0,%1,%2,%3};"
        : "+f"(d[0]), "+f"(d[1]), "+f"(d[2]), "+f"(d[3])
        : "r"(a[0]), "r"(a[1]), "r"(a[2]), "r"(a[3]), "r"(b0), "r"(b1));
}

// ---------------- merged zero + weight prep ----------------
__global__ void k_prep(const float* __restrict__ w1re, const float* __restrict__ w1im,
                       const float* __restrict__ w2re, const float* __restrict__ w2im) {
    int idx = blockIdx.x * blockDim.x + threadIdx.x;
    if (idx < NR) { g_rcount[idx] = 0; g_ucnt[idx] = 0; }
    if (idx >= 4*FD*FD) return;
    int mat = idx >> 14;
    int rem = idx & (FD*FD - 1);
    int n = rem >> 7, k = rem & 127;
    const float* W = (mat == 0) ? w1re : (mat == 1) ? w1im : (mat == 2) ? w2re : w2im;
    g_Wf[mat][n*FD + k] = __float2half_rn(W[k*FD + n]);
}

__global__ void k_count(const int* __restrict__ mask) {
    __shared__ int scnt[2*NR];
    int t = threadIdx.x;
    for (int i = t; i < 2*NR; i += 256) scnt[i] = 0;
    __syncthreads();
    int base = blockIdx.x * 1024;
    #pragma unroll
    for (int i = 0; i < 4; i++) {
        int p = base + i*256 + t;
        int r = ring_of(p);
        int m = mask[p];
        atomicAdd(&scnt[r], 1);
        if (m == 0) atomicAdd(&scnt[NR + r], 1);
    }
    __syncthreads();
    for (int i = t; i < NR; i += 256) {
        int c = scnt[i];       if (c) atomicAdd(&g_rcount[i], c);
        int u = scnt[NR + i];  if (u) atomicAdd(&g_ucnt[i], u);
    }
}

// two scans: uncor prefix and cor prefix
__global__ void k_scan() {
    __shared__ int s[512];
    int t = threadIdx.x;
    s[t] = (t < NR) ? g_ucnt[t] : 0;
    __syncthreads();
    #pragma unroll
    for (int d = 1; d < 512; d <<= 1) {
        int x = (t >= d) ? s[t - d] : 0;
        __syncthreads();
        s[t] += x;
        __syncthreads();
    }
    int ub = (t == 0) ? 0 : s[t - 1];
    int total_u = s[511];
    if (t < NR) { g_base[t] = ub; g_cur[t] = ub; }
    if (t == 0) {
        g_base[NR] = total_u;
        g_cnt[0]   = total_u;
        g_cnt[1]   = NPIX - total_u;
    }
    __syncthreads();
    s[t] = (t < NR) ? (g_rcount[t] - g_ucnt[t]) : 0;
    __syncthreads();
    #pragma unroll
    for (int d = 1; d < 512; d <<= 1) {
        int x = (t >= d) ? s[t - d] : 0;
        __syncthreads();
        s[t] += x;
        __syncthreads();
    }
    int cb = (t == 0) ? 0 : s[t - 1];
    if (t < NR) g_cur[NR + t] = cb;
}

// scatter into ring-grouped lists, BOTH types bucketed by ring
__global__ void k_scatter(const int* __restrict__ mask) {
    __shared__ int lcnt[2*NR];
    __shared__ int sbase[2*NR];
    int t = threadIdx.x;
    for (int i = t; i < 2*NR; i += 256) lcnt[i] = 0;
    __syncthreads();
    int base = blockIdx.x * 1024;
    int key[4], lpos[4];
    #pragma unroll
    for (int i = 0; i < 4; i++) {
        int p = base + i*256 + t;
        int m = mask[p];
        key[i] = ring_of(p) + (m ? NR : 0);
        lpos[i] = atomicAdd(&lcnt[key[i]], 1);
    }
    __syncthreads();
    for (int i = t; i < 2*NR; i += 256) {
        int c = lcnt[i];
        if (c) sbase[i] = atomicAdd(&g_cur[i], c);
    }
    __syncthreads();
    #pragma unroll
    for (int i = 0; i < 4; i++) {
        int p = base + i*256 + t;
        int pos = sbase[key[i]] + lpos[i];
        if (key[i] >= NR) g_list[1][pos] = p;
        else              g_list[0][pos] = p;
    }
}

// atomic-free ring sums: grid (NR, 8), block 128
__global__ void k_ringsum(const float* __restrict__ img_re,
                          const float* __restrict__ img_im) {
    __shared__ float sred[4][32];
    int r = blockIdx.x, g = blockIdx.y;
    int t = threadIdx.x, lane = t & 31, wid = t >> 5;
    int b0 = g_base[r], n = g_base[r+1] - b0;
    const int* lst = g_list[0] + b0;
    float ar[16], ai[16];
    #pragma unroll
    for (int f = 0; f < 16; f++) { ar[f] = 0.f; ai[f] = 0.f; }
    for (int i = t; i < n; i += 128) {
        int p = lst[i];
        const float4* pr = (const float4*)(img_re + (size_t)p*FD + g*16);
        const float4* pi = (const float4*)(img_im + (size_t)p*FD + g*16);
        #pragma unroll
        for (int c = 0; c < 4; c++) {
            float4 v = pr[c];
            ar[c*4+0] += v.x; ar[c*4+1] += v.y; ar[c*4+2] += v.z; ar[c*4+3] += v.w;
            v = pi[c];
            ai[c*4+0] += v.x; ai[c*4+1] += v.y; ai[c*4+2] += v.z; ai[c*4+3] += v.w;
        }
    }
    #pragma unroll
    for (int f = 0; f < 16; f++) {
        #pragma unroll
        for (int m = 16; m > 0; m >>= 1) {
            ar[f] += __shfl_xor_sync(0xFFFFFFFF, ar[f], m);
            ai[f] += __shfl_xor_sync(0xFFFFFFFF, ai[f], m);
        }
    }
    if (lane == 0) {
        #pragma unroll
        for (int f = 0; f < 16; f++) {
            sred[wid][f]      = ar[f];
            sred[wid][16 + f] = ai[f];
        }
    }
    __syncthreads();
    if (t < 32) {
        float s = sred[0][t] + sred[1][t] + sred[2][t] + sred[3][t];
        int f = t & 15;
        if (t < 16) g_sum_re[r*FD + g*16 + f] = s;
        else        g_sum_im[r*FD + g*16 + f] = s;
    }
}

// ring means: block 512 = 4 k-slices x 128 features
__global__ void k_ringmm(const float* __restrict__ w1re,
                         const float* __restrict__ w1im) {
    __shared__ float sre[FD], sim[FD];
    __shared__ float pre[4][FD], pim[4][FD];
    int r = blockIdx.x, t = threadIdx.x;
    int sl = t >> 7, f = t & 127;
    if (t < 256) {
        if (t < 128) sre[t] = g_sum_re[r*FD + t];
        else         sim[t - 128] = g_sum_im[r*FD + t - 128];
    }
    __syncthreads();
    float accr = 0.f, acci = 0.f;
    #pragma unroll 8
    for (int kk = 0; kk < 32; kk++) {
        int k = sl*32 + kk;
        float wr = w1re[k*FD + f];
        float wi = w1im[k*FD + f];
        accr += sre[k]*wr - sim[k]*wi;
        acci += sre[k]*wi + sim[k]*wr;
    }
    pre[sl][f] = accr;
    pim[sl][f] = acci;
    __syncthreads();
    if (t < 256) {
        float c = (float)max(g_rcount[r], 1);
        int ff = t & 127;
        if (t < 128) g_mean_re[r*FD + ff] = (pre[0][ff]+pre[1][ff]+pre[2][ff]+pre[3][ff]) / c;
        else         g_mean_im[r*FD + ff] = (pim[0][ff]+pim[1][ff]+pim[2][ff]+pim[3][ff]) / c;
    }
}

// ---------------- main GEMM: N-split fp16 HMMA, BM=32, 4 CTA/SM ----------------
// Each CTA computes a 64-feature N-half. Consecutive block ids = two halves of
// the same tile (wave-paired -> second A read hits L2).
// A segs: 0=Xr 1=Xi; -Xi via register XOR.
// accR = Xr@Wr + (-Xi)@Wi ; accI = Xr@Wi + Xi@Wr
__global__ __launch_bounds__(GEMM_THREADS, 4)
void k_gemm(const float* __restrict__ img_re, const float* __restrict__ img_im,
            float* __restrict__ out) {
    extern __shared__ char sm[];
    const int t = threadIdx.x, lane = t & 31, wid = t >> 5;
    const int warp_m = wid >> 2;          // 0..1 (16 rows each)
    const int warp_n = wid & 3;           // 0..3 (16 cols each within the half)

    const int nh    = blockIdx.x & 1;     // N-half
    const int pair  = blockIdx.x >> 1;    // 0..295
    const int type  = (pair >= TYPE_GRID) ? 1 : 0;
    const int bid_t = type ? pair - TYPE_GRID : pair;
    const int cnt   = g_cnt[type];
    const int T     = (cnt + BM - 1) >> 5;
    const int* lst  = g_list[type];

    uint32_t smb = smem_u32(sm);
    int* s_p    = (int*)(sm + OFF_P);
    int* s_ring = (int*)(sm + OFF_RING);

    const int row = t >> 3, q = t & 7;    // 8 threads per A row (32 rows)

    // ---- stage B: Wr, Wi for this N-half, transposed, swizzled (resident) ----
    {
        const __half* srcs[2] = { g_Wf[2*type], g_Wf[2*type+1] };
        #pragma unroll 4
        for (int i = t; i < 2*1024; i += GEMM_THREADS) {
            int mat = i >> 10, g = i & 1023;
            int nl = g >> 4, u = g & 15;
            uint4 v = ((const uint4*)srcs[mat])[(nh*64 + nl)*16 + u];
            *(uint4*)(sm + OFF_B + mat*MATB + nl*256 + phys_unit(u, nl)*16) = v;
        }
    }

    for (int tile = bid_t; tile < T; tile += TYPE_GRID) {
        __syncthreads();   // prev compute done before A rewrite

        // ---- stage A: batched gather loads, then convert+store ----
        {
            int grow = tile*BM + row;
            int p = -1, rg = 0;
            if (grow < cnt) { p = lst[grow]; rg = ring_of(p); }
            if (q == 0) { s_p[row] = p; s_ring[row] = rg; }
            const float4* ar = (const float4*)(img_re + (size_t)(p < 0 ? 0 : p) * FD);
            const float4* ai = (const float4*)(img_im + (size_t)(p < 0 ? 0 : p) * FD);
            float4 z = make_float4(0.f, 0.f, 0.f, 0.f);
            float4 vr[4], vi[4];
            #pragma unroll
            for (int i = 0; i < 4; i++) {
                vr[i] = (p >= 0) ? ar[q*4 + i] : z;
                vi[i] = (p >= 0) ? ai[q*4 + i] : z;
            }
            #pragma unroll
            for (int i = 0; i < 4; i++) {
                int k4 = q*4 + i;
                int u  = k4 >> 1;
                uint32_t base = (uint32_t)(row*256 + phys_unit(u, row)*16 + (k4 & 1)*8);
                __half2 r01 = __floats2half2_rn(vr[i].x, vr[i].y);
                __half2 r23 = __floats2half2_rn(vr[i].z, vr[i].w);
                __half2 i01 = __floats2half2_rn(vi[i].x, vi[i].y);
                __half2 i23 = __floats2half2_rn(vi[i].z, vi[i].w);
                *(uint2*)(sm + OFF_A + base)        = make_uint2(*(uint32_t*)&r01, *(uint32_t*)&r23);
                *(uint2*)(sm + OFF_A + SEGA + base) = make_uint2(*(uint32_t*)&i01, *(uint32_t*)&i23);
            }
        }

        // ---- L2 prefetch of next tile's gathered rows (half 0 only; shared) ----
        if (nh == 0) {
            int ntile = tile + TYPE_GRID;
            int grow = ntile*BM + row;
            if (ntile < T && grow < cnt) {
                int p2 = lst[grow];
                if (q < 4) {
                    const char* pr = (const char*)(img_re + (size_t)p2 * FD) + q*128;
                    asm volatile("prefetch.global.L2 [%0];" :: "l"(pr));
                } else {
                    const char* pi = (const char*)(img_im + (size_t)p2 * FD) + (q-4)*128;
                    asm volatile("prefetch.global.L2 [%0];" :: "l"(pi));
                }
            }
        }
        __syncthreads();

        // ---- compute: 16 n per warp ----
        float accR[2][4], accI[2][4];
        #pragma unroll
        for (int nt = 0; nt < 2; nt++)
            #pragma unroll
            for (int e = 0; e < 4; e++) { accR[nt][e] = 0.f; accI[nt][e] = 0.f; }

        #pragma unroll
        for (int ks = 0; ks < 8; ks++) {
            uint32_t axr[4], axi[4], an[4];
            {
                int rr = warp_m*16 + (lane & 15);
                int u  = 2*ks + (lane >> 4);
                uint32_t addr = smb + OFF_A + (uint32_t)(rr*256 + phys_unit(u, rr)*16);
                LDSM_X4(axr, addr);
                LDSM_X4(axi, addr + SEGA);
            }
            #pragma unroll
            for (int e = 0; e < 4; e++) an[e] = axi[e] ^ 0x80008000u;
            {
                int nl = warp_n*16 + (lane & 7) + ((lane & 16) ? 8 : 0);
                int u  = 2*ks + ((lane & 8) ? 1 : 0);
                uint32_t addr = smb + OFF_B + (uint32_t)(nl*256 + phys_unit(u, nl)*16);
                uint32_t b0[4], b1[4];
                LDSM_X4(b0, addr);
                LDSM_X4(b1, addr + MATB);
                mma4(accR[0], axr, b0[0], b0[1]);
                mma4(accR[1], axr, b0[2], b0[3]);
                mma4(accR[0], an,  b1[0], b1[1]);
                mma4(accR[1], an,  b1[2], b1[3]);
                mma4(accI[0], axr, b1[0], b1[1]);
                mma4(accI[1], axr, b1[2], b1[3]);
                mma4(accI[0], axi, b0[0], b0[1]);
                mma4(accI[1], axi, b0[2], b0[3]);
            }
        }

        // ---- fused epilogue: 16 features of this half ----
        #pragma unroll
        for (int rv = 0; rv < 2; rv++) {
            int r = warp_m*16 + rv*8 + (lane >> 2);
            int p = s_p[r];
            if (p < 0) continue;
            int ring = s_ring[r];
            const float* mre = g_mean_re + ring*FD;
            const float* mim = g_mean_im + ring*FD;
            float* op = out + (size_t)p * 256;
            #pragma unroll
            for (int nt = 0; nt < 2; nt++) {
                int c = nh*64 + warp_n*16 + nt*8 + (lane & 3)*2;
                float re0 = accR[nt][rv*2 + 0], re1 = accR[nt][rv*2 + 1];
                float im0 = accI[nt][rv*2 + 0], im1 = accI[nt][rv*2 + 1];
                float2 mr = *(const float2*)&mre[c];
                float2 mi = *(const float2*)&mim[c];
                float4 o;
                if (type == 0) {
                    o.x = 0.5f*(re0 + mr.x); o.y = 0.5f*(im0 + mi.x);
                    o.z = 0.5f*(re1 + mr.y); o.w = 0.5f*(im1 + mi.y);
                } else {
                    o.x = re0 - mr.x; o.y = im0 - mi.x;
                    o.z = re1 - mr.y; o.w = im1 - mi.y;
                }
                *(float4*)&op[c*2] = o;
            }
        }
    }
}

// ---------------- launch ----------------
extern "C" void kernel_launch(void* const* d_in, const int* in_sizes, int n_in,
                              void* d_out, int out_size) {
    const float* img_re = (const float*)d_in[0];
    const float* img_im = (const float*)d_in[1];
    const int*   mask   = (const int*)  d_in[2];
    const float* w1re   = (const float*)d_in[5];
    const float* w1im   = (const float*)d_in[6];
    const float* w2re   = (const float*)d_in[7];
    const float* w2im   = (const float*)d_in[8];
    float* out = (float*)d_out;

    k_prep<<<(4*FD*FD + 255)/256, 256>>>(w1re, w1im, w2re, w2im);
    k_count<<<NPIX/1024, 256>>>(mask);
    k_scan<<<1, 512>>>();
    k_scatter<<<NPIX/1024, 256>>>(mask);
    k_ringsum<<<dim3(NR, 8), 128>>>(img_re, img_im);
    k_ringmm<<<NR, 512>>>(w1re, w1im);

    cudaFuncSetAttribute(k_gemm, cudaFuncAttributeMaxDynamicSharedMemorySize, SMEM_TOTAL);
    k_gemm<<<GEMM_GRID, GEMM_THREADS, SMEM_TOTAL>>>(img_re, img_im, out);
}

// round 17
// speedup vs baseline: 1.2750x; 1.2750x over previous
#include <cuda_runtime.h>
#include <cuda_fp16.h>
#include <math.h>
#include <stdint.h>

#define HH    512
#define NPIX  (HH*HH)
#define FD    128
#define NR    363
#define BM    32
#define GEMM_THREADS 256
#define GEMM_GRID 296      // 2 per SM
#define HALF_GRID (GEMM_GRID/2)

// k_gemm smem layout (2 CTAs/SM, ~81KB each, ~66KB L1 left)
#define OFF_P    0                           // int[32]
#define OFF_RING 128                         // int[32]
#define OFF_A    1024                        // 2 segs: Xr, Xi
#define SEGA     8192                        // 32 rows x 256B fp16
#define OFF_B    (OFF_A + 2*SEGA)            // 17408
#define MATB     32768                       // 128n x 256B fp16
#define SMEM_TOTAL (OFF_B + 2*MATB)          // 82944 (~81KB)

// ---------------- device scratch ----------------
__device__ float g_sum_re[NR*FD];
__device__ float g_sum_im[NR*FD];
__device__ float g_mean_re[NR*FD];
__device__ float g_mean_im[NR*FD];
__device__ int   g_rcount[NR];
__device__ int   g_ucnt[NR];
__device__ int   g_base[NR+1];     // uncor ring bases (for ringsum)
__device__ int   g_cur[2*NR];      // scatter cursors
__device__ int   g_cnt[2];
__device__ int   g_list[2][NPIX];  // both lists ring-grouped
__device__ __align__(16) __half g_Wf[4][FD*FD];   // 0=w1re 1=w1im 2=w2re 3=w2im, [n*128+k]

// ---------------- helpers ----------------
__device__ __forceinline__ int ring_of(int p) {
    int i = (p >> 9) - 256;
    int j = (p & 511) - 256;
    int q = i*i + j*j;
    int s = __float2int_rd(sqrtf((float)q));
    while (s*s > q) --s;
    while ((s+1)*(s+1) <= q) ++s;
    return s;
}

__device__ __forceinline__ uint32_t smem_u32(const void* p) {
    uint32_t a;
    asm("{ .reg .u64 t; cvta.to.shared.u64 t, %1; cvt.u32.u64 %0, t; }" : "=r"(a) : "l"(p));
    return a;
}

// 16B-unit XOR swizzle within 256B rows
__device__ __forceinline__ int phys_unit(int u, int row) {
    return (u & 8) | ((u & 7) ^ (row & 7));
}

#define LDSM_X4(r, addr) \
    asm volatile("ldmatrix.sync.aligned.m8n8.x4.shared.b16 {%0,%1,%2,%3}, [%4];" \
        : "=r"((r)[0]), "=r"((r)[1]), "=r"((r)[2]), "=r"((r)[3]) : "r"(addr))

__device__ __forceinline__ void mma4(float* d, const uint32_t* a, uint32_t b0, uint32_t b1) {
    asm volatile("mma.sync.aligned.m16n8k16.row.col.f32.f16.f16.f32 "
        "{%0,%1,%2,%3}, {%4,%5,%6,%7}, {%8,%9}, {%0,%1,%2,%3};"
        : "+f"(d[0]), "+f"(d[1]), "+f"(d[2]), "+f"(d[3])
        : "r"(a[0]), "r"(a[1]), "r"(a[2]), "r"(a[3]), "r"(b0), "r"(b1));
}

// ---------------- merged zero + weight prep ----------------
__global__ void k_prep(const float* __restrict__ w1re, const float* __restrict__ w1im,
                       const float* __restrict__ w2re, const float* __restrict__ w2im) {
    int idx = blockIdx.x * blockDim.x + threadIdx.x;
    if (idx < NR) { g_rcount[idx] = 0; g_ucnt[idx] = 0; }
    if (idx >= 4*FD*FD) return;
    int mat = idx >> 14;
    int rem = idx & (FD*FD - 1);
    int n = rem >> 7, k = rem & 127;
    const float* W = (mat == 0) ? w1re : (mat == 1) ? w1im : (mat == 2) ? w2re : w2im;
    g_Wf[mat][n*FD + k] = __float2half_rn(W[k*FD + n]);
}

__global__ void k_count(const int* __restrict__ mask) {
    __shared__ int scnt[2*NR];
    int t = threadIdx.x;
    for (int i = t; i < 2*NR; i += 256) scnt[i] = 0;
    __syncthreads();
    int base = blockIdx.x * 1024;
    #pragma unroll
    for (int i = 0; i < 4; i++) {
        int p = base + i*256 + t;
        int r = ring_of(p);
        int m = mask[p];
        atomicAdd(&scnt[r], 1);
        if (m == 0) atomicAdd(&scnt[NR + r], 1);
    }
    __syncthreads();
    for (int i = t; i < NR; i += 256) {
        int c = scnt[i];       if (c) atomicAdd(&g_rcount[i], c);
        int u = scnt[NR + i];  if (u) atomicAdd(&g_ucnt[i], u);
    }
}

// two scans: uncor prefix and cor prefix
__global__ void k_scan() {
    __shared__ int s[512];
    int t = threadIdx.x;
    s[t] = (t < NR) ? g_ucnt[t] : 0;
    __syncthreads();
    #pragma unroll
    for (int d = 1; d < 512; d <<= 1) {
        int x = (t >= d) ? s[t - d] : 0;
        __syncthreads();
        s[t] += x;
        __syncthreads();
    }
    int ub = (t == 0) ? 0 : s[t - 1];
    int total_u = s[511];
    if (t < NR) { g_base[t] = ub; g_cur[t] = ub; }
    if (t == 0) {
        g_base[NR] = total_u;
        g_cnt[0]   = total_u;
        g_cnt[1]   = NPIX - total_u;
    }
    __syncthreads();
    s[t] = (t < NR) ? (g_rcount[t] - g_ucnt[t]) : 0;
    __syncthreads();
    #pragma unroll
    for (int d = 1; d < 512; d <<= 1) {
        int x = (t >= d) ? s[t - d] : 0;
        __syncthreads();
        s[t] += x;
        __syncthreads();
    }
    int cb = (t == 0) ? 0 : s[t - 1];
    if (t < NR) g_cur[NR + t] = cb;
}

// scatter into ring-grouped lists, BOTH types bucketed by ring
__global__ void k_scatter(const int* __restrict__ mask) {
    __shared__ int lcnt[2*NR];
    __shared__ int sbase[2*NR];
    int t = threadIdx.x;
    for (int i = t; i < 2*NR; i += 256) lcnt[i] = 0;
    __syncthreads();
    int base = blockIdx.x * 1024;
    int key[4], lpos[4];
    #pragma unroll
    for (int i = 0; i < 4; i++) {
        int p = base + i*256 + t;
        int m = mask[p];
        key[i] = ring_of(p) + (m ? NR : 0);
        lpos[i] = atomicAdd(&lcnt[key[i]], 1);
    }
    __syncthreads();
    for (int i = t; i < 2*NR; i += 256) {
        int c = lcnt[i];
        if (c) sbase[i] = atomicAdd(&g_cur[i], c);
    }
    __syncthreads();
    #pragma unroll
    for (int i = 0; i < 4; i++) {
        int p = base + i*256 + t;
        int pos = sbase[key[i]] + lpos[i];
        if (key[i] >= NR) g_list[1][pos] = p;
        else              g_list[0][pos] = p;
    }
}

// atomic-free ring sums: grid (NR, 8), block 128
__global__ void k_ringsum(const float* __restrict__ img_re,
                          const float* __restrict__ img_im) {
    __shared__ float sred[4][32];
    int r = blockIdx.x, g = blockIdx.y;
    int t = threadIdx.x, lane = t & 31, wid = t >> 5;
    int b0 = g_base[r], n = g_base[r+1] - b0;
    const int* lst = g_list[0] + b0;
    float ar[16], ai[16];
    #pragma unroll
    for (int f = 0; f < 16; f++) { ar[f] = 0.f; ai[f] = 0.f; }
    for (int i = t; i < n; i += 128) {
        int p = lst[i];
        const float4* pr = (const float4*)(img_re + (size_t)p*FD + g*16);
        const float4* pi = (const float4*)(img_im + (size_t)p*FD + g*16);
        #pragma unroll
        for (int c = 0; c < 4; c++) {
            float4 v = pr[c];
            ar[c*4+0] += v.x; ar[c*4+1] += v.y; ar[c*4+2] += v.z; ar[c*4+3] += v.w;
            v = pi[c];
            ai[c*4+0] += v.x; ai[c*4+1] += v.y; ai[c*4+2] += v.z; ai[c*4+3] += v.w;
        }
    }
    #pragma unroll
    for (int f = 0; f < 16; f++) {
        #pragma unroll
        for (int m = 16; m > 0; m >>= 1) {
            ar[f] += __shfl_xor_sync(0xFFFFFFFF, ar[f], m);
            ai[f] += __shfl_xor_sync(0xFFFFFFFF, ai[f], m);
        }
    }
    if (lane == 0) {
        #pragma unroll
        for (int f = 0; f < 16; f++) {
            sred[wid][f]      = ar[f];
            sred[wid][16 + f] = ai[f];
        }
    }
    __syncthreads();
    if (t < 32) {
        float s = sred[0][t] + sred[1][t] + sred[2][t] + sred[3][t];
        int f = t & 15;
        if (t < 16) g_sum_re[r*FD + g*16 + f] = s;
        else        g_sum_im[r*FD + g*16 + f] = s;
    }
}

// ring means: block 512 = 4 k-slices x 128 features
__global__ void k_ringmm(const float* __restrict__ w1re,
                         const float* __restrict__ w1im) {
    __shared__ float sre[FD], sim[FD];
    __shared__ float pre[4][FD], pim[4][FD];
    int r = blockIdx.x, t = threadIdx.x;
    int sl = t >> 7, f = t & 127;
    if (t < 256) {
        if (t < 128) sre[t] = g_sum_re[r*FD + t];
        else         sim[t - 128] = g_sum_im[r*FD + t - 128];
    }
    __syncthreads();
    float accr = 0.f, acci = 0.f;
    #pragma unroll 8
    for (int kk = 0; kk < 32; kk++) {
        int k = sl*32 + kk;
        float wr = w1re[k*FD + f];
        float wi = w1im[k*FD + f];
        accr += sre[k]*wr - sim[k]*wi;
        acci += sre[k]*wi + sim[k]*wr;
    }
    pre[sl][f] = accr;
    pim[sl][f] = acci;
    __syncthreads();
    if (t < 256) {
        float c = (float)max(g_rcount[r], 1);
        int ff = t & 127;
        if (t < 128) g_mean_re[r*FD + ff] = (pre[0][ff]+pre[1][ff]+pre[2][ff]+pre[3][ff]) / c;
        else         g_mean_im[r*FD + ff] = (pim[0][ff]+pim[1][ff]+pim[2][ff]+pim[3][ff]) / c;
    }
}

// ---------------- main GEMM: register-pipelined gather, fp16 HMMA, BM=32, 2 CTA/SM ----------------
// Gather LDGs for tile t+1 issue right after tile t's A is staged; results sit
// in registers (scoreboard) through the whole compute phase -> zero exposed
// DRAM latency at staging, no group-wide waits.
// A segs: 0=Xr 1=Xi; -Xi via register XOR.
// accR = Xr@Wr + (-Xi)@Wi ; accI = Xr@Wi + Xi@Wr
__global__ __launch_bounds__(GEMM_THREADS, 2)
void k_gemm(const float* __restrict__ img_re, const float* __restrict__ img_im,
            float* __restrict__ out) {
    extern __shared__ char sm[];
    const int t = threadIdx.x, lane = t & 31, wid = t >> 5;
    const int warp_m = wid >> 2;          // 0..1 (16 rows each)
    const int warp_n = wid & 3;           // 0..3 (32 cols each)

    const int type  = (blockIdx.x >= HALF_GRID) ? 1 : 0;
    const int bid_t = type ? blockIdx.x - HALF_GRID : blockIdx.x;
    const int cnt   = g_cnt[type];
    const int T     = (cnt + BM - 1) >> 5;
    const int* lst  = g_list[type];
    if (bid_t >= T) return;

    uint32_t smb = smem_u32(sm);
    int* s_p    = (int*)(sm + OFF_P);
    int* s_ring = (int*)(sm + OFF_RING);

    const int row = t >> 3, q = t & 7;    // 8 threads per A row (32 rows)

    // ---- stage B: Wr, Wi fp16 transposed, swizzled (resident) ----
    {
        const __half* srcs[2] = { g_Wf[2*type], g_Wf[2*type+1] };
        #pragma unroll 4
        for (int i = t; i < 2*2048; i += GEMM_THREADS) {
            int mat = i >> 11, g = i & 2047;
            int n = g >> 4, u = g & 15;
            uint4 v = ((const uint4*)srcs[mat])[g];
            *(uint4*)(sm + OFF_B + mat*MATB + n*256 + phys_unit(u, n)*16) = v;
        }
    }

    // register pipeline state: raw fp32 rows for the NEXT tile to stage
    float4 vr[4], vi[4];
    int pp = -1;
    {
        int grow = bid_t*BM + row;
        float4 z = make_float4(0.f, 0.f, 0.f, 0.f);
        if (grow < cnt) {
            pp = lst[grow];
            const float4* ar = (const float4*)(img_re + (size_t)pp * FD);
            const float4* ai = (const float4*)(img_im + (size_t)pp * FD);
            #pragma unroll
            for (int i = 0; i < 4; i++) { vr[i] = ar[q*4 + i]; vi[i] = ai[q*4 + i]; }
        } else {
            #pragma unroll
            for (int i = 0; i < 4; i++) { vr[i] = z; vi[i] = z; }
        }
    }

    for (int tile = bid_t; tile < T; tile += HALF_GRID) {
        __syncthreads();   // prev compute done before A rewrite

        // ---- stage A from registers (convert+STS, no memory wait) ----
        if (q == 0) { s_p[row] = pp; s_ring[row] = (pp >= 0) ? ring_of(pp) : 0; }
        #pragma unroll
        for (int i = 0; i < 4; i++) {
            int k4 = q*4 + i;
            int u  = k4 >> 1;
            uint32_t base = (uint32_t)(row*256 + phys_unit(u, row)*16 + (k4 & 1)*8);
            __half2 r01 = __floats2half2_rn(vr[i].x, vr[i].y);
            __half2 r23 = __floats2half2_rn(vr[i].z, vr[i].w);
            __half2 i01 = __floats2half2_rn(vi[i].x, vi[i].y);
            __half2 i23 = __floats2half2_rn(vi[i].z, vi[i].w);
            *(uint2*)(sm + OFF_A + base)        = make_uint2(*(uint32_t*)&r01, *(uint32_t*)&r23);
            *(uint2*)(sm + OFF_A + SEGA + base) = make_uint2(*(uint32_t*)&i01, *(uint32_t*)&i23);
        }
        __syncthreads();   // A ready

        // ---- issue gather LDGs for next tile (consumed next iteration) ----
        {
            int ntile = tile + HALF_GRID;
            int grow = ntile*BM + row;
            float4 z = make_float4(0.f, 0.f, 0.f, 0.f);
            pp = -1;
            if (ntile < T && grow < cnt) {
                pp = lst[grow];
                const float4* ar = (const float4*)(img_re + (size_t)pp * FD);
                const float4* ai = (const float4*)(img_im + (size_t)pp * FD);
                #pragma unroll
                for (int i = 0; i < 4; i++) { vr[i] = ar[q*4 + i]; vi[i] = ai[q*4 + i]; }
            } else {
                #pragma unroll
                for (int i = 0; i < 4; i++) { vr[i] = z; vi[i] = z; }
            }
        }

        // ---- compute: 4-product complex, accR/accI [4][4] ----
        float accR[4][4], accI[4][4];
        #pragma unroll
        for (int nt = 0; nt < 4; nt++)
            #pragma unroll
            for (int e = 0; e < 4; e++) { accR[nt][e] = 0.f; accI[nt][e] = 0.f; }

        #pragma unroll
        for (int ks = 0; ks < 8; ks++) {
            uint32_t axr[4], axi[4], an[4];
            {
                int rr = warp_m*16 + (lane & 15);
                int u  = 2*ks + (lane >> 4);
                uint32_t addr = smb + OFF_A + (uint32_t)(rr*256 + phys_unit(u, rr)*16);
                LDSM_X4(axr, addr);
                LDSM_X4(axi, addr + SEGA);
            }
            #pragma unroll
            for (int e = 0; e < 4; e++) an[e] = axi[e] ^ 0x80008000u;
            #pragma unroll
            for (int n2 = 0; n2 < 2; n2++) {
                int n = warp_n*32 + n2*16 + (lane & 7) + ((lane & 16) ? 8 : 0);
                int u = 2*ks + ((lane & 8) ? 1 : 0);
                uint32_t addr = smb + OFF_B + (uint32_t)(n*256 + phys_unit(u, n)*16);
                uint32_t b0[4], b1[4];
                LDSM_X4(b0, addr);
                LDSM_X4(b1, addr + MATB);
                mma4(accR[n2*2 + 0], axr, b0[0], b0[1]);
                mma4(accR[n2*2 + 1], axr, b0[2], b0[3]);
                mma4(accR[n2*2 + 0], an,  b1[0], b1[1]);
                mma4(accR[n2*2 + 1], an,  b1[2], b1[3]);
                mma4(accI[n2*2 + 0], axr, b1[0], b1[1]);
                mma4(accI[n2*2 + 1], axr, b1[2], b1[3]);
                mma4(accI[n2*2 + 0], axi, b0[0], b0[1]);
                mma4(accI[n2*2 + 1], axi, b0[2], b0[3]);
            }
        }

        // ---- fused epilogue ----
        #pragma unroll
        for (int rv = 0; rv < 2; rv++) {
            int r = warp_m*16 + rv*8 + (lane >> 2);
            int p = s_p[r];
            if (p < 0) continue;
            int ring = s_ring[r];
            const float* mre = g_mean_re + ring*FD;
            const float* mim = g_mean_im + ring*FD;
            float* op = out + (size_t)p * 256;
            #pragma unroll
            for (int nt = 0; nt < 4; nt++) {
                int c = warp_n*32 + nt*8 + (lane & 3)*2;
                float re0 = accR[nt][rv*2 + 0], re1 = accR[nt][rv*2 + 1];
                float im0 = accI[nt][rv*2 + 0], im1 = accI[nt][rv*2 + 1];
                float2 mr = *(const float2*)&mre[c];
                float2 mi = *(const float2*)&mim[c];
                float4 o;
                if (type == 0) {
                    o.x = 0.5f*(re0 + mr.x); o.y = 0.5f*(im0 + mi.x);
                    o.z = 0.5f*(re1 + mr.y); o.w = 0.5f*(im1 + mi.y);
                } else {
                    o.x = re0 - mr.x; o.y = im0 - mi.x;
                    o.z = re1 - mr.y; o.w = im1 - mi.y;
                }
                *(float4*)&op[c*2] = o;
            }
        }
    }
}

// ---------------- launch ----------------
extern "C" void kernel_launch(void* const* d_in, const int* in_sizes, int n_in,
                              void* d_out, int out_size) {
    const float* img_re = (const float*)d_in[0];
    const float* img_im = (const float*)d_in[1];
    const int*   mask   = (const int*)  d_in[2];
    const float* w1re   = (const float*)d_in[5];
    const float* w1im   = (const float*)d_in[6];
    const float* w2re   = (const float*)d_in[7];
    const float* w2im   = (const float*)d_in[8];
    float* out = (float*)d_out;

    k_prep<<<(4*FD*FD + 255)/256, 256>>>(w1re, w1im, w2re, w2im);
    k_count<<<NPIX/1024, 256>>>(mask);
    k_scan<<<1, 512>>>();
    k_scatter<<<NPIX/1024, 256>>>(mask);
    k_ringsum<<<dim3(NR, 8), 128>>>(img_re, img_im);
    k_ringmm<<<NR, 512>>>(w1re, w1im);

    cudaFuncSetAttribute(k_gemm, cudaFuncAttributeMaxDynamicSharedMemorySize, SMEM_TOTAL);
    k_gemm<<<GEMM_GRID, GEMM_THREADS, SMEM_TOTAL>>>(img_re, img_im, out);
}